// round 14
// baseline (speedup 1.0000x reference)
#include <cuda_runtime.h>

#define S_DIM 100000
#define G_DIM 18000
#define H_DIM 256
#define E_DIM 600000
#define B_DIM 256

#define G4_DIM  4500   // G_DIM/4 float4 columns
#define BSTRIPS 36     // gene strips of 128 float4 (2KB)
#define BKT     8      // k-tiles (32 k's each)
#define CHUNKS  50     // gemv chunks along S
#define ROWS    8      // gemv rows per block
#define SCAT_BLOCKS 586   // ceil(150000/256)
#define C0_BLOCKS   9     // const0 tail blocks

#define PF_NBLK  384           // prefetch kernel blocks
#define PF_PER_THR 4           // lines per thread -> 384*256*4 = 393216 lines (50.3 MB)

// INVARIANT: g_v == 0 at every kernel_launch entry (statically zero at load;
// k_gemv re-zeroes it on exit when v is dead). k_build_v's grid.y==BKT slice
// zeroes coef/out/const0 before their writers run.
__device__ float g_v[G_DIM];
__device__ float g_coef[S_DIM];
__device__ float g_const0;

__device__ __forceinline__ void l2_prefetch(const char* p) {
    asm volatile("prefetch.global.L2 [%0];" :: "l"(p));
}

// ---------------------------------------------------------------------------
// Parallel-branch kernel: stage the first 50 MB of x into L2 while the
// latency-bound build_v -> scatter chain runs on the main stream.
__global__ void __launch_bounds__(256)
k_xpf(const float* __restrict__ x) {
    const char* xb = reinterpret_cast<const char*>(x);
    unsigned t = blockIdx.x * 256 + threadIdx.x;
    #pragma unroll
    for (int j = 0; j < PF_PER_THR; j++) {
        unsigned line = t + j * (PF_NBLK * 256);
        l2_prefetch(xb + (size_t)line * 128);
    }
}

// ---------------------------------------------------------------------------
// Kernel 1: grid=(BSTRIPS, BKT+1), block=256 (8 warps). Proven R12 layout.
//   y < BKT : build_v tile (2KB warp spans, smem reduce). W1 via __ldcs
//             (evict-first: don't evict staged x lines).
//   y == BKT: zero coef + out + const0.
__global__ void __launch_bounds__(256, 4)
k_build_v(const float* __restrict__ W1, const float* __restrict__ W2,
          float* __restrict__ out) {
    if (blockIdx.y == BKT) {
        float4 z = make_float4(0.f, 0.f, 0.f, 0.f);
        float4* c4 = reinterpret_cast<float4*>(g_coef);
        for (int i = blockIdx.x * 256 + threadIdx.x; i < S_DIM / 4; i += BSTRIPS * 256)
            c4[i] = z;
        if (blockIdx.x == 0) {
            out[threadIdx.x] = 0.0f;                 // B_DIM == 256
            if (threadIdx.x == 0) g_const0 = 0.0f;
        }
        return;
    }
    const int w  = threadIdx.x >> 5;
    const int tx = threadIdx.x & 31;
    const int k0 = blockIdx.y * 32;
    const int gbase = blockIdx.x * 128;              // float4 index

    __shared__ float  w2s[32];
    __shared__ float4 red[8][4][32];                 // 16 KB
    if (threadIdx.x < 32) w2s[threadIdx.x] = W2[k0 + threadIdx.x];
    __syncthreads();

    const float4* __restrict__ W14 = reinterpret_cast<const float4*>(W1);
    float4 acc[4];
    #pragma unroll
    for (int j = 0; j < 4; j++) acc[j] = make_float4(0.f, 0.f, 0.f, 0.f);

    #pragma unroll
    for (int s = 0; s < 4; s++) {
        const int k = k0 + w + 8 * s;
        const float sw = w2s[w + 8 * s];
        const float4* __restrict__ row = W14 + (size_t)k * G4_DIM + gbase;
        #pragma unroll
        for (int j = 0; j < 4; j++) {
            if (gbase + 32 * j + tx < G4_DIM) {
                float4 wv = __ldcs(row + 32 * j + tx);   // streaming: evict-first
                acc[j].x = fmaf(wv.x, sw, acc[j].x);
                acc[j].y = fmaf(wv.y, sw, acc[j].y);
                acc[j].z = fmaf(wv.z, sw, acc[j].z);
                acc[j].w = fmaf(wv.w, sw, acc[j].w);
            }
        }
    }

    #pragma unroll
    for (int j = 0; j < 4; j++) red[w][j][tx] = acc[j];
    __syncthreads();

    if (w < 4) {
        const int j = w;
        float4 a = red[0][j][tx];
        #pragma unroll
        for (int r = 1; r < 8; r++) {
            float4 o = red[r][j][tx];
            a.x += o.x; a.y += o.y; a.z += o.z; a.w += o.w;
        }
        const int g4 = gbase + 32 * j + tx;
        if (g4 < G4_DIM) {
            float* vo = &g_v[g4 * 4];
            atomicAdd(vo + 0, a.x);
            atomicAdd(vo + 1, a.y);
            atomicAdd(vo + 2, a.z);
            atomicAdd(vo + 3, a.w);
        }
    }
}

// ---------------------------------------------------------------------------
// Kernel 2: edge scatter (streaming loads) + const0 tail blocks.
__global__ void k_scatter(const int* __restrict__ snp, const int* __restrict__ gidx,
                          const float* __restrict__ ew,
                          const float* __restrict__ gene_bias,
                          const float* __restrict__ b1, const float* __restrict__ W2,
                          const float* __restrict__ b2) {
    if (blockIdx.x < SCAT_BLOCKS) {
        int i4 = blockIdx.x * blockDim.x + threadIdx.x;     // quad index
        if (i4 >= E_DIM / 4) return;
        int4   s4 = __ldcs(reinterpret_cast<const int4*>(snp) + i4);
        int4   g4 = __ldcs(reinterpret_cast<const int4*>(gidx) + i4);
        float4 w4 = __ldcs(reinterpret_cast<const float4*>(ew) + i4);
        float v0 = g_v[g4.x], v1 = g_v[g4.y], v2 = g_v[g4.z], v3 = g_v[g4.w];
        atomicAdd(&g_coef[s4.x], w4.x * v0);
        atomicAdd(&g_coef[s4.y], w4.y * v1);
        atomicAdd(&g_coef[s4.z], w4.z * v2);
        atomicAdd(&g_coef[s4.w], w4.w * v3);
        return;
    }
    // ---- const0 tail ----
    int local = blockIdx.x - SCAT_BLOCKS;                   // 0..8
    int start = local * (G_DIM / C0_BLOCKS);                // 2000 per block
    float acc = 0.0f;
    for (int g = start + threadIdx.x; g < start + G_DIM / C0_BLOCKS; g += blockDim.x)
        acc = fmaf(g_v[g], gene_bias[g], acc);
    if (local == 0) {
        acc = fmaf(W2[threadIdx.x], b1[threadIdx.x], acc);  // blockDim == H_DIM
        if (threadIdx.x == 0) acc += b2[0];
    }
    __shared__ float sm[32];
    int lane = threadIdx.x & 31, wid = threadIdx.x >> 5;
    #pragma unroll
    for (int o = 16; o > 0; o >>= 1) acc += __shfl_down_sync(0xffffffffu, acc, o);
    if (lane == 0) sm[wid] = acc;
    __syncthreads();
    if (wid == 0) {
        acc = (lane < (blockDim.x >> 5)) ? sm[lane] : 0.0f;
        #pragma unroll
        for (int o = 16; o > 0; o >>= 1) acc += __shfl_down_sync(0xffffffffu, acc, o);
        if (lane == 0) atomicAdd(&g_const0, acc);
    }
}

// ---------------------------------------------------------------------------
// Kernel 3: GEMV (frozen proven config). grid=(50,32)=1600.
// ~50 MB of x is L2-resident from the parallel prefetch branch.
__global__ void __launch_bounds__(256, 6)
k_gemv(const float* __restrict__ x, float* __restrict__ out) {
    const int per  = (S_DIM / 4) / CHUNKS;         // 500
    const int base = blockIdx.x * per;
    const int r0   = blockIdx.y * ROWS;
    const float4* __restrict__ cf = reinterpret_cast<const float4*>(g_coef);

    float acc[ROWS];
    #pragma unroll
    for (int j = 0; j < ROWS; j++) acc[j] = 0.0f;

    #pragma unroll
    for (int it = 0; it < 2; it++) {
        int off = it * 256 + threadIdx.x;
        if (off < per) {
            int i = base + off;
            float4 cv = __ldg(&cf[i]);
            #pragma unroll
            for (int j = 0; j < ROWS; j++) {
                float4 xv = __ldcs(reinterpret_cast<const float4*>(
                                x + (size_t)(r0 + j) * S_DIM) + i);
                acc[j] += xv.x * cv.x + xv.y * cv.y + xv.z * cv.z + xv.w * cv.w;
            }
        }
    }

    __shared__ float sm[ROWS][8];
    int lane = threadIdx.x & 31, wid = threadIdx.x >> 5;
    #pragma unroll
    for (int j = 0; j < ROWS; j++) {
        float v = acc[j];
        #pragma unroll
        for (int o = 16; o > 0; o >>= 1) v += __shfl_down_sync(0xffffffffu, v, o);
        if (lane == 0) sm[j][wid] = v;
    }
    __syncthreads();
    if (threadIdx.x < ROWS * 8) {
        int j = threadIdx.x >> 3, w = threadIdx.x & 7;
        float v = sm[j][w];
        #pragma unroll
        for (int o = 4; o > 0; o >>= 1) v += __shfl_down_sync(0xffffffffu, v, o);
        if (w == 0) {
            if (blockIdx.x == 0) v += g_const0;
            atomicAdd(&out[r0 + j], v);
        }
    }

    // ---- epilogue: restore g_v == 0 for the next kernel_launch call ----
    if (blockIdx.x == 0) {
        int i = blockIdx.y * 256 + threadIdx.x;
        #pragma unroll
        for (int rep = 0; rep < 3; rep++, i += 8192)
            if (i < G_DIM) g_v[i] = 0.0f;
    }
}

// ---------------------------------------------------------------------------
extern "C" void kernel_launch(void* const* d_in, const int* in_sizes, int n_in,
                              void* d_out, int out_size) {
    const float* x    = (const float*)d_in[0];
    const int*   snp  = (const int*)  d_in[1];
    const int*   gidx = (const int*)  d_in[2];
    const float* ew   = (const float*)d_in[3];
    const float* gb   = (const float*)d_in[4];
    const float* W1   = (const float*)d_in[5];
    const float* b1   = (const float*)d_in[6];
    const float* W2   = (const float*)d_in[7];
    const float* b2   = (const float*)d_in[8];
    float* out = (float*)d_out;

    // One-time host-side resources (no device memory involved). The same
    // stream/events are reused on every call -> identical graph each capture.
    static cudaStream_t s2 = nullptr;
    static cudaEvent_t  e_fork = nullptr, e_join = nullptr;
    if (s2 == nullptr) {
        cudaStreamCreateWithFlags(&s2, cudaStreamNonBlocking);
        cudaEventCreateWithFlags(&e_fork, cudaEventDisableTiming);
        cudaEventCreateWithFlags(&e_join, cudaEventDisableTiming);
    }

    // Fork: prefetch branch runs concurrently with the build_v -> scatter chain.
    cudaEventRecord(e_fork, 0);
    cudaStreamWaitEvent(s2, e_fork, 0);
    k_xpf<<<PF_NBLK, 256, 0, s2>>>(x);
    cudaEventRecord(e_join, s2);

    // Main chain.
    k_build_v<<<dim3(BSTRIPS, BKT + 1), 256>>>(W1, W2, out);
    k_scatter<<<SCAT_BLOCKS + C0_BLOCKS, 256>>>(snp, gidx, ew, gb, b1, W2, b2);

    // Join before gemv (also closes the forked branch for graph capture).
    cudaStreamWaitEvent(0, e_join, 0);
    k_gemv<<<dim3(CHUNKS, B_DIM / ROWS), 256>>>(x, out);
}

// round 15
// speedup vs baseline: 1.0589x; 1.0589x over previous
#include <cuda_runtime.h>

#define S_DIM 100000
#define G_DIM 18000
#define H_DIM 256
#define E_DIM 600000
#define B_DIM 256

#define G4_DIM  4500   // G_DIM/4 float4 columns
#define BSTRIPS 36     // gene strips of 128 float4 (2KB)
#define BKT     8      // k-tiles (32 k's each)
#define CHUNKS  50     // gemv chunks along S
#define ROWS    8      // gemv rows per block
#define SCAT_BLOCKS 586   // ceil(150000/256)
#define C0_BLOCKS   9     // const0 tail blocks
#define PF_BLOCKS  64     // x-prefetch blocks appended to scatter grid

#define X_LINES    800000 // 102.4 MB / 128B
#define PF1_LINES_PER_THR 10           // build_v slice: 36*256*10 = 92160 lines (11.8MB)
#define PF1_TOTAL (BSTRIPS * 256 * PF1_LINES_PER_THR)
#define PF2_LINES_PER_THR 4            // scatter: 64*256*4 = 65536 lines (8.4MB)

// INVARIANT: g_v == 0 at every kernel_launch entry (statically zero at load;
// k_gemv re-zeroes it on exit when v is dead). k_build_v's grid.y==BKT slice
// zeroes coef/out/const0 before their writers run.
__device__ float g_v[G_DIM];
__device__ float g_coef[S_DIM];
__device__ float g_const0;

__device__ __forceinline__ void l2_prefetch(const char* p) {
    asm volatile("prefetch.global.L2 [%0];" :: "l"(p));
}

// ---------------------------------------------------------------------------
// Kernel 1: grid=(BSTRIPS, BKT+2), block=256 (8 warps).
//   y < BKT  : build_v tile (proven layout: 2KB warp spans, smem reduce)
//   y == BKT : zero coef + out + const0
//   y == BKT+1: L2-prefetch x lines [0, PF1_TOTAL) — sized to the free
//              bandwidth window of the latency-bound build blocks.
__global__ void __launch_bounds__(256, 4)
k_build_v(const float* __restrict__ W1, const float* __restrict__ W2,
          float* __restrict__ out, const float* __restrict__ x) {
    if (blockIdx.y == BKT) {
        float4 z = make_float4(0.f, 0.f, 0.f, 0.f);
        float4* c4 = reinterpret_cast<float4*>(g_coef);
        for (int i = blockIdx.x * 256 + threadIdx.x; i < S_DIM / 4; i += BSTRIPS * 256)
            c4[i] = z;
        if (blockIdx.x == 0) {
            out[threadIdx.x] = 0.0f;                 // B_DIM == 256
            if (threadIdx.x == 0) g_const0 = 0.0f;
        }
        return;
    }
    if (blockIdx.y == BKT + 1) {
        const char* xb = reinterpret_cast<const char*>(x);
        int t = blockIdx.x * 256 + threadIdx.x;      // 0..9215
        #pragma unroll
        for (int j = 0; j < PF1_LINES_PER_THR; j++) {
            int line = t + j * (BSTRIPS * 256);
            l2_prefetch(xb + (size_t)line * 128);
        }
        return;
    }
    const int w  = threadIdx.x >> 5;
    const int tx = threadIdx.x & 31;
    const int k0 = blockIdx.y * 32;
    const int gbase = blockIdx.x * 128;              // float4 index

    __shared__ float  w2s[32];
    __shared__ float4 red[8][4][32];                 // 16 KB
    if (threadIdx.x < 32) w2s[threadIdx.x] = W2[k0 + threadIdx.x];
    __syncthreads();

    const float4* __restrict__ W14 = reinterpret_cast<const float4*>(W1);
    float4 acc[4];
    #pragma unroll
    for (int j = 0; j < 4; j++) acc[j] = make_float4(0.f, 0.f, 0.f, 0.f);

    #pragma unroll
    for (int s = 0; s < 4; s++) {
        const int k = k0 + w + 8 * s;
        const float sw = w2s[w + 8 * s];
        const float4* __restrict__ row = W14 + (size_t)k * G4_DIM + gbase;
        #pragma unroll
        for (int j = 0; j < 4; j++) {
            if (gbase + 32 * j + tx < G4_DIM) {
                float4 wv = __ldcs(row + 32 * j + tx);   // streaming: evict-first
                acc[j].x = fmaf(wv.x, sw, acc[j].x);
                acc[j].y = fmaf(wv.y, sw, acc[j].y);
                acc[j].z = fmaf(wv.z, sw, acc[j].z);
                acc[j].w = fmaf(wv.w, sw, acc[j].w);
            }
        }
    }

    #pragma unroll
    for (int j = 0; j < 4; j++) red[w][j][tx] = acc[j];
    __syncthreads();

    if (w < 4) {
        const int j = w;
        float4 a = red[0][j][tx];
        #pragma unroll
        for (int r = 1; r < 8; r++) {
            float4 o = red[r][j][tx];
            a.x += o.x; a.y += o.y; a.z += o.z; a.w += o.w;
        }
        const int g4 = gbase + 32 * j + tx;
        if (g4 < G4_DIM) {
            float* vo = &g_v[g4 * 4];
            atomicAdd(vo + 0, a.x);
            atomicAdd(vo + 1, a.y);
            atomicAdd(vo + 2, a.z);
            atomicAdd(vo + 3, a.w);
        }
    }
}

// ---------------------------------------------------------------------------
// Kernel 2: edge scatter + const0 tail + x-prefetch blocks (free window).
__global__ void k_scatter(const int* __restrict__ snp, const int* __restrict__ gidx,
                          const float* __restrict__ ew,
                          const float* __restrict__ gene_bias,
                          const float* __restrict__ b1, const float* __restrict__ W2,
                          const float* __restrict__ b2, const float* __restrict__ x) {
    if (blockIdx.x < SCAT_BLOCKS) {
        int i4 = blockIdx.x * blockDim.x + threadIdx.x;     // quad index
        if (i4 >= E_DIM / 4) return;
        int4   s4 = __ldcs(reinterpret_cast<const int4*>(snp) + i4);
        int4   g4 = __ldcs(reinterpret_cast<const int4*>(gidx) + i4);
        float4 w4 = __ldcs(reinterpret_cast<const float4*>(ew) + i4);
        float v0 = g_v[g4.x], v1 = g_v[g4.y], v2 = g_v[g4.z], v3 = g_v[g4.w];
        atomicAdd(&g_coef[s4.x], w4.x * v0);
        atomicAdd(&g_coef[s4.y], w4.y * v1);
        atomicAdd(&g_coef[s4.z], w4.z * v2);
        atomicAdd(&g_coef[s4.w], w4.w * v3);
        return;
    }
    if (blockIdx.x >= SCAT_BLOCKS + C0_BLOCKS) {
        // ---- x prefetch: lines [PF1_TOTAL, PF1_TOTAL + 64*256*4) ----
        const char* xb = reinterpret_cast<const char*>(x);
        int t = (blockIdx.x - SCAT_BLOCKS - C0_BLOCKS) * 256 + threadIdx.x;
        #pragma unroll
        for (int j = 0; j < PF2_LINES_PER_THR; j++) {
            int line = PF1_TOTAL + t + j * (PF_BLOCKS * 256);
            if (line < X_LINES) l2_prefetch(xb + (size_t)line * 128);
        }
        return;
    }
    // ---- const0 tail ----
    int local = blockIdx.x - SCAT_BLOCKS;                   // 0..8
    int start = local * (G_DIM / C0_BLOCKS);                // 2000 per block
    float acc = 0.0f;
    for (int g = start + threadIdx.x; g < start + G_DIM / C0_BLOCKS; g += blockDim.x)
        acc = fmaf(g_v[g], gene_bias[g], acc);
    if (local == 0) {
        acc = fmaf(W2[threadIdx.x], b1[threadIdx.x], acc);  // blockDim == H_DIM
        if (threadIdx.x == 0) acc += b2[0];
    }
    __shared__ float sm[32];
    int lane = threadIdx.x & 31, wid = threadIdx.x >> 5;
    #pragma unroll
    for (int o = 16; o > 0; o >>= 1) acc += __shfl_down_sync(0xffffffffu, acc, o);
    if (lane == 0) sm[wid] = acc;
    __syncthreads();
    if (wid == 0) {
        acc = (lane < (blockDim.x >> 5)) ? sm[lane] : 0.0f;
        #pragma unroll
        for (int o = 16; o > 0; o >>= 1) acc += __shfl_down_sync(0xffffffffu, acc, o);
        if (lane == 0) atomicAdd(&g_const0, acc);
    }
}

// ---------------------------------------------------------------------------
// Kernel 3: GEMV (frozen proven config). grid=(50,32)=1600.
// ~20 MB of x is L2-resident from the free-window prefetches.
__global__ void __launch_bounds__(256, 6)
k_gemv(const float* __restrict__ x, float* __restrict__ out) {
    const int per  = (S_DIM / 4) / CHUNKS;         // 500
    const int base = blockIdx.x * per;
    const int r0   = blockIdx.y * ROWS;
    const float4* __restrict__ cf = reinterpret_cast<const float4*>(g_coef);

    float acc[ROWS];
    #pragma unroll
    for (int j = 0; j < ROWS; j++) acc[j] = 0.0f;

    #pragma unroll
    for (int it = 0; it < 2; it++) {
        int off = it * 256 + threadIdx.x;
        if (off < per) {
            int i = base + off;
            float4 cv = __ldg(&cf[i]);
            #pragma unroll
            for (int j = 0; j < ROWS; j++) {
                float4 xv = __ldcs(reinterpret_cast<const float4*>(
                                x + (size_t)(r0 + j) * S_DIM) + i);
                acc[j] += xv.x * cv.x + xv.y * cv.y + xv.z * cv.z + xv.w * cv.w;
            }
        }
    }

    __shared__ float sm[ROWS][8];
    int lane = threadIdx.x & 31, wid = threadIdx.x >> 5;
    #pragma unroll
    for (int j = 0; j < ROWS; j++) {
        float v = acc[j];
        #pragma unroll
        for (int o = 16; o > 0; o >>= 1) v += __shfl_down_sync(0xffffffffu, v, o);
        if (lane == 0) sm[j][wid] = v;
    }
    __syncthreads();
    if (threadIdx.x < ROWS * 8) {
        int j = threadIdx.x >> 3, w = threadIdx.x & 7;
        float v = sm[j][w];
        #pragma unroll
        for (int o = 4; o > 0; o >>= 1) v += __shfl_down_sync(0xffffffffu, v, o);
        if (w == 0) {
            if (blockIdx.x == 0) v += g_const0;
            atomicAdd(&out[r0 + j], v);
        }
    }

    // ---- epilogue: restore g_v == 0 for the next kernel_launch call ----
    if (blockIdx.x == 0) {
        int i = blockIdx.y * 256 + threadIdx.x;
        #pragma unroll
        for (int rep = 0; rep < 3; rep++, i += 8192)
            if (i < G_DIM) g_v[i] = 0.0f;
    }
}

// ---------------------------------------------------------------------------
extern "C" void kernel_launch(void* const* d_in, const int* in_sizes, int n_in,
                              void* d_out, int out_size) {
    const float* x    = (const float*)d_in[0];
    const int*   snp  = (const int*)  d_in[1];
    const int*   gidx = (const int*)  d_in[2];
    const float* ew   = (const float*)d_in[3];
    const float* gb   = (const float*)d_in[4];
    const float* W1   = (const float*)d_in[5];
    const float* b1   = (const float*)d_in[6];
    const float* W2   = (const float*)d_in[7];
    const float* b2   = (const float*)d_in[8];
    float* out = (float*)d_out;

    k_build_v<<<dim3(BSTRIPS, BKT + 2), 256>>>(W1, W2, out, x);
    k_scatter<<<SCAT_BLOCKS + C0_BLOCKS + PF_BLOCKS, 256>>>(snp, gidx, ew, gb, b1, W2, b2, x);
    k_gemv<<<dim3(CHUNKS, B_DIM / ROWS), 256>>>(x, out);
}